// round 6
// baseline (speedup 1.0000x reference)
#include <cuda_runtime.h>
#include <cstdint>
#include <math.h>

#define BB 8
#define NN 2048
#define DD 128
#define KK 64
#define TT 64
#define TILES 32   // NN / TT

// per-tile partials (fully rewritten every launch -> no zero kernel)
__device__ float g_Pp[BB * TILES * KK * DD];   // 8 MB
__device__ float g_sp[BB * TILES * KK];

#define STR  132  // smem row stride (floats) for Cs/xs
#define STRA 68   // smem row stride for At (n=64 + pad)

// smem float offsets
#define O_CN2 0
#define O_SSM 64
#define O_CS  128
#define O_AT  (O_CS + KK * STR)      // 64*132
#define O_XS  (O_AT + KK * STRA)     // 64*68
#define SMF   (O_XS + TT * STR)      // 128+8448+4352+8448 = 21376 floats = 85504 B

__device__ __forceinline__ uint32_t tf32r(float f) {
    uint32_t u;
    asm("cvt.rna.tf32.f32 %0, %1;" : "=r"(u) : "f"(f));
    return u;
}
__device__ __forceinline__ void mma8(float* d, const uint32_t* a, const uint32_t* b) {
    asm volatile(
        "mma.sync.aligned.m16n8k8.row.col.f32.tf32.tf32.f32 "
        "{%0,%1,%2,%3}, {%4,%5,%6,%7}, {%8,%9}, {%0,%1,%2,%3};"
        : "+f"(d[0]), "+f"(d[1]), "+f"(d[2]), "+f"(d[3])
        : "r"(a[0]), "r"(a[1]), "r"(a[2]), "r"(a[3]), "r"(b[0]), "r"(b[1]));
}

// ---------------------------------------------------------------------------
// Main: one 64-row tile per CTA. grid = (32 tiles, 8 batches), 256 threads,
// 2 CTAs per SM (85.5KB smem each). Warp w owns n in [8w,8w+8) for
// GEMM1/softmax and d in [16w,16w+16) for GEMM2.
// ---------------------------------------------------------------------------
__global__ __launch_bounds__(256, 2)
void nv_main(const float* __restrict__ x, const float* __restrict__ cent) {
    extern __shared__ float sm[];
    float* cn2 = sm + O_CN2;
    float* ssm = sm + O_SSM;
    float* Cs  = sm + O_CS;
    float* At  = sm + O_AT;
    float* xs  = sm + O_XS;

    const int tid = threadIdx.x, w = tid >> 5, l = tid & 31;
    const int b = blockIdx.y, tile = blockIdx.x;
    const int r0 = l >> 2, c0 = l & 3;
    const int nb = w * 8;

    if (tid < 64) ssm[tid] = 0.f;

    // ---- phase A: load C (tf32-rounded) and raw x tile ----
    {
        const float4* c4 = (const float4*)cent;
        #pragma unroll
        for (int i = tid; i < KK * DD / 4; i += 256) {
            float4 v = c4[i];
            int k = i >> 5, d4 = (i & 31) * 4;
            float* dst = &Cs[k * STR + d4];
            dst[0] = __uint_as_float(tf32r(v.x));
            dst[1] = __uint_as_float(tf32r(v.y));
            dst[2] = __uint_as_float(tf32r(v.z));
            dst[3] = __uint_as_float(tf32r(v.w));
        }
        const float4* x4 = (const float4*)(x + ((size_t)b * NN + (size_t)tile * TT) * DD);
        #pragma unroll
        for (int i = tid; i < TT * 32; i += 256) {
            float4 v = x4[i];
            int n = i >> 5, d4 = (i & 31) * 4;
            *(float4*)&xs[n * STR + d4] = v;
        }
    }
    __syncthreads();

    // ---- phase B: cn2[k] = ||c_k||^2 ; L2-normalize x rows in place + tf32 round ----
    {
        int k = tid >> 2, q = tid & 3;
        float s = 0.f;
        #pragma unroll
        for (int j = 0; j < 8; j++) {
            float4 v = *(float4*)&Cs[k * STR + q * 32 + 4 * j];
            s += v.x * v.x + v.y * v.y + v.z * v.z + v.w * v.w;
        }
        s += __shfl_xor_sync(~0u, s, 1);
        s += __shfl_xor_sync(~0u, s, 2);
        if (q == 0) cn2[k] = s;
    }
    {
        #pragma unroll
        for (int r = w * 8; r < w * 8 + 8; r++) {
            float4 v = *(float4*)&xs[r * STR + 4 * l];
            float ss = v.x * v.x + v.y * v.y + v.z * v.z + v.w * v.w;
            #pragma unroll
            for (int o = 16; o; o >>= 1) ss += __shfl_xor_sync(~0u, ss, o);
            float ri = 1.f / fmaxf(sqrtf(ss), 1e-12f);
            v.x = __uint_as_float(tf32r(v.x * ri));
            v.y = __uint_as_float(tf32r(v.y * ri));
            v.z = __uint_as_float(tf32r(v.z * ri));
            v.w = __uint_as_float(tf32r(v.w * ri));
            *(float4*)&xs[r * STR + 4 * l] = v;
        }
    }
    __syncthreads();

    // ---- GEMM1: S^T[k][n] = C[k][d] * xn[n][d]^T ; warp w: n in [8w,8w+8) ----
    float acc[4][4];
    #pragma unroll
    for (int mt = 0; mt < 4; mt++)
        #pragma unroll
        for (int q = 0; q < 4; q++) acc[mt][q] = 0.f;

    #pragma unroll
    for (int s = 0; s < 16; s++) {
        const int col = s * 8 + c0;
        uint32_t a[4][4], bf[2];
        #pragma unroll
        for (int mt = 0; mt < 4; mt++) {
            const float* p = &Cs[(mt * 16 + r0) * STR + col];
            a[mt][0] = __float_as_uint(p[0]);
            a[mt][1] = __float_as_uint(p[8 * STR]);
            a[mt][2] = __float_as_uint(p[4]);
            a[mt][3] = __float_as_uint(p[8 * STR + 4]);
        }
        {
            const float* p = &xs[(nb + r0) * STR + col];
            bf[0] = __float_as_uint(p[0]);
            bf[1] = __float_as_uint(p[4]);
        }
        #pragma unroll
        for (int mt = 0; mt < 4; mt++) mma8(acc[mt], a[mt], bf);
    }

    // ---- softmax per n-column over k=64 (within warp) ----
    // dist = cn2[k] - 2*S (||xn||^2 shift dropped: softmax shift-invariant)
    float mx0 = -1e30f, mx1 = -1e30f;
    #pragma unroll
    for (int mt = 0; mt < 4; mt++) {
        float cA = cn2[mt * 16 + r0], cB = cn2[mt * 16 + r0 + 8];
        acc[mt][0] = cA - 2.f * acc[mt][0];
        acc[mt][1] = cA - 2.f * acc[mt][1];
        acc[mt][2] = cB - 2.f * acc[mt][2];
        acc[mt][3] = cB - 2.f * acc[mt][3];
        mx0 = fmaxf(mx0, fmaxf(acc[mt][0], acc[mt][2]));
        mx1 = fmaxf(mx1, fmaxf(acc[mt][1], acc[mt][3]));
    }
    #pragma unroll
    for (int o = 4; o <= 16; o <<= 1) {
        mx0 = fmaxf(mx0, __shfl_xor_sync(~0u, mx0, o));
        mx1 = fmaxf(mx1, __shfl_xor_sync(~0u, mx1, o));
    }
    float s0 = 0.f, s1 = 0.f;
    #pragma unroll
    for (int mt = 0; mt < 4; mt++) {
        acc[mt][0] = __expf(acc[mt][0] - mx0);
        acc[mt][1] = __expf(acc[mt][1] - mx1);
        acc[mt][2] = __expf(acc[mt][2] - mx0);
        acc[mt][3] = __expf(acc[mt][3] - mx1);
        s0 += acc[mt][0] + acc[mt][2];
        s1 += acc[mt][1] + acc[mt][3];
    }
    #pragma unroll
    for (int o = 4; o <= 16; o <<= 1) {
        s0 += __shfl_xor_sync(~0u, s0, o);
        s1 += __shfl_xor_sync(~0u, s1, o);
    }
    s0 = 1.f / s0;
    s1 = 1.f / s1;

    // assign -> At[k][n] (tf32-rounded) + row sums -> ssm
    #pragma unroll
    for (int mt = 0; mt < 4; mt++) {
        float a0 = acc[mt][0] * s0, a1 = acc[mt][1] * s1;
        float a2 = acc[mt][2] * s0, a3 = acc[mt][3] * s1;
        float rs0 = a0 + a1, rs1 = a2 + a3;
        int rr = mt * 16 + r0, cc = nb + 2 * c0;
        At[rr * STRA + cc]           = __uint_as_float(tf32r(a0));
        At[rr * STRA + cc + 1]       = __uint_as_float(tf32r(a1));
        At[(rr + 8) * STRA + cc]     = __uint_as_float(tf32r(a2));
        At[(rr + 8) * STRA + cc + 1] = __uint_as_float(tf32r(a3));
        rs0 += __shfl_xor_sync(~0u, rs0, 1);
        rs0 += __shfl_xor_sync(~0u, rs0, 2);
        rs1 += __shfl_xor_sync(~0u, rs1, 1);
        rs1 += __shfl_xor_sync(~0u, rs1, 2);
        if (c0 == 0) {
            atomicAdd(&ssm[rr], rs0);
            atomicAdd(&ssm[rr + 8], rs1);
        }
    }
    __syncthreads();

    // ---- GEMM2: P[k][d] = At[k][n] * Xn[n][d] ; warp w: d in [16w,16w+16) ----
    // B operand read straight from row-major xs with swapped indices
    // (bank = 4*c0 + r0 + const: conflict-free).
    const int db = w * 16;
    float pc[4][2][4];
    #pragma unroll
    for (int mt = 0; mt < 4; mt++)
        #pragma unroll
        for (int nt = 0; nt < 2; nt++)
            #pragma unroll
            for (int q = 0; q < 4; q++) pc[mt][nt][q] = 0.f;

    #pragma unroll
    for (int s = 0; s < 8; s++) {
        const int col = s * 8 + c0;
        uint32_t a[4][4], bf0[2], bf1[2];
        #pragma unroll
        for (int mt = 0; mt < 4; mt++) {
            const float* p = &At[(mt * 16 + r0) * STRA + col];
            a[mt][0] = __float_as_uint(p[0]);
            a[mt][1] = __float_as_uint(p[8 * STRA]);
            a[mt][2] = __float_as_uint(p[4]);
            a[mt][3] = __float_as_uint(p[8 * STRA + 4]);
        }
        bf0[0] = __float_as_uint(xs[col * STR + db + r0]);
        bf0[1] = __float_as_uint(xs[(col + 4) * STR + db + r0]);
        bf1[0] = __float_as_uint(xs[col * STR + db + 8 + r0]);
        bf1[1] = __float_as_uint(xs[(col + 4) * STR + db + 8 + r0]);
        #pragma unroll
        for (int mt = 0; mt < 4; mt++) {
            mma8(pc[mt][0], a[mt], bf0);
            mma8(pc[mt][1], a[mt], bf1);
        }
    }

    // store per-tile partials
    float* Pb = g_Pp + (size_t)(b * TILES + tile) * KK * DD;
    #pragma unroll
    for (int mt = 0; mt < 4; mt++)
        #pragma unroll
        for (int nt = 0; nt < 2; nt++) {
            int rr = mt * 16 + r0, dd2 = db + nt * 8 + 2 * c0;
            *(float2*)&Pb[rr * DD + dd2]       = make_float2(pc[mt][nt][0], pc[mt][nt][1]);
            *(float2*)&Pb[(rr + 8) * DD + dd2] = make_float2(pc[mt][nt][2], pc[mt][nt][3]);
        }
    if (tid < 64) g_sp[(b * TILES + tile) * KK + tid] = ssm[tid];
}

// ---------------------------------------------------------------------------
// fin: grid (b=8, k=64) = 512 blocks, 128 threads (thread = d element).
// Reduce 32 tile partials (MLP-32, coalesced), v = P - s*c, intra-normalize,
// exact global scale 1/8 (64 unit k-vectors => global norm = 8).
// ---------------------------------------------------------------------------
__global__ __launch_bounds__(128, 8)
void nv_fin(const float* __restrict__ cent, float* __restrict__ out) {
    __shared__ float ps[4];
    const int b = blockIdx.x, k = blockIdx.y;
    const int d = threadIdx.x, l = d & 31, wi = d >> 5;

    float acc = 0.f;
    #pragma unroll
    for (int t = 0; t < TILES; t++)
        acc += g_Pp[((size_t)(b * TILES + t) * KK + k) * DD + d];

    // s[k] = sum over 32 tiles (lane t loads tile t; warp-redundant)
    float sv = g_sp[(b * TILES + l) * KK + k];
    #pragma unroll
    for (int o = 16; o; o >>= 1) sv += __shfl_xor_sync(~0u, sv, o);

    float v = acc - sv * cent[k * DD + d];
    float ssq = v * v;
    #pragma unroll
    for (int o = 16; o; o >>= 1) ssq += __shfl_xor_sync(~0u, ssq, o);
    if (l == 0) ps[wi] = ssq;
    __syncthreads();
    float tot = ps[0] + ps[1] + ps[2] + ps[3];
    float sc = 0.125f / fmaxf(sqrtf(tot), 1e-12f);
    out[(size_t)b * KK * DD + k * DD + d] = v * sc;
}

// ---------------------------------------------------------------------------
extern "C" void kernel_launch(void* const* d_in, const int* in_sizes, int n_in,
                              void* d_out, int out_size) {
    (void)in_sizes; (void)n_in; (void)out_size;
    const float* x    = (const float*)d_in[0];
    const float* cent = (const float*)d_in[1];
    float* out        = (float*)d_out;

    cudaFuncSetAttribute(nv_main, cudaFuncAttributeMaxDynamicSharedMemorySize,
                         (int)(SMF * sizeof(float)));
    nv_main<<<dim3(TILES, BB), 256, SMF * sizeof(float)>>>(x, cent);
    nv_fin<<<dim3(BB, KK), 128>>>(cent, out);
}

// round 7
// speedup vs baseline: 1.0135x; 1.0135x over previous
#include <cuda_runtime.h>
#include <cstdint>
#include <math.h>

#define BB 8
#define NN 2048
#define DD 128
#define KK 64
#define TT 64
#define TILES 32   // NN / TT

// per-tile partials (fully rewritten every launch -> no zero kernel)
__device__ float g_Pp[BB * TILES * KK * DD];   // 8 MB
__device__ float g_sp[BB * TILES * KK];

#define STR  132  // smem row stride (floats) for Cs/xs
#define STRA 68   // smem row stride for At (n=64 + pad)

// smem float offsets
#define O_CN2 0
#define O_SSM 64
#define O_CS  128
#define O_AT  (O_CS + KK * STR)      // 64*132
#define O_XS  (O_AT + KK * STRA)     // 64*68
#define SMF   (O_XS + TT * STR)      // 21376 floats = 85504 B

__device__ __forceinline__ uint32_t tf32r(float f) {
    uint32_t u;
    asm("cvt.rna.tf32.f32 %0, %1;" : "=r"(u) : "f"(f));
    return u;
}
__device__ __forceinline__ void mma8(float* d, const uint32_t* a, const uint32_t* b) {
    asm volatile(
        "mma.sync.aligned.m16n8k8.row.col.f32.tf32.tf32.f32 "
        "{%0,%1,%2,%3}, {%4,%5,%6,%7}, {%8,%9}, {%0,%1,%2,%3};"
        : "+f"(d[0]), "+f"(d[1]), "+f"(d[2]), "+f"(d[3])
        : "r"(a[0]), "r"(a[1]), "r"(a[2]), "r"(a[3]), "r"(b[0]), "r"(b[1]));
}

// ---------------------------------------------------------------------------
// Main: one 64-row tile per CTA. grid = (32 tiles, 8 batches), 256 threads,
// 2 CTAs per SM (85.5KB smem each). Warp w owns n in [8w,8w+8) for
// GEMM1/softmax and d in [16w,16w+16) for GEMM2.
// ---------------------------------------------------------------------------
__global__ __launch_bounds__(256, 2)
void nv_main(const float* __restrict__ x, const float* __restrict__ cent) {
    extern __shared__ float sm[];
    float* cn2 = sm + O_CN2;
    float* ssm = sm + O_SSM;
    float* Cs  = sm + O_CS;
    float* At  = sm + O_AT;
    float* xs  = sm + O_XS;

    const int tid = threadIdx.x, w = tid >> 5, l = tid & 31;
    const int b = blockIdx.y, tile = blockIdx.x;
    const int r0 = l >> 2, c0 = l & 3;
    const int nb = w * 8;

    if (tid < 64) ssm[tid] = 0.f;

    // ---- phase A: load C (tf32-rounded); load x rows to regs, L2-normalize,
    //      single smem write (no raw round trip). Warp w owns rows 8w..8w+8. ----
    {
        const float4* x4 = (const float4*)(x + ((size_t)b * NN + (size_t)tile * TT) * DD);
        float4 xv[8];
        #pragma unroll
        for (int i = 0; i < 8; i++) xv[i] = x4[(w * 8 + i) * 32 + l];

        const float4* c4 = (const float4*)cent;
        #pragma unroll
        for (int i = tid; i < KK * DD / 4; i += 256) {
            float4 v = c4[i];
            int k = i >> 5, d4 = (i & 31) * 4;
            float* dst = &Cs[k * STR + d4];
            dst[0] = __uint_as_float(tf32r(v.x));
            dst[1] = __uint_as_float(tf32r(v.y));
            dst[2] = __uint_as_float(tf32r(v.z));
            dst[3] = __uint_as_float(tf32r(v.w));
        }

        #pragma unroll
        for (int i = 0; i < 8; i++) {
            float4 v = xv[i];
            float ss = v.x * v.x + v.y * v.y + v.z * v.z + v.w * v.w;
            #pragma unroll
            for (int o = 16; o; o >>= 1) ss += __shfl_xor_sync(~0u, ss, o);
            float ri = 1.f / fmaxf(sqrtf(ss), 1e-12f);
            float* dst = &xs[(w * 8 + i) * STR + 4 * l];
            dst[0] = __uint_as_float(tf32r(v.x * ri));
            dst[1] = __uint_as_float(tf32r(v.y * ri));
            dst[2] = __uint_as_float(tf32r(v.z * ri));
            dst[3] = __uint_as_float(tf32r(v.w * ri));
        }
    }
    __syncthreads();

    // ---- phase B: cn2[k] = ||c_k||^2 ----
    {
        int k = tid >> 2, q = tid & 3;
        float s = 0.f;
        #pragma unroll
        for (int j = 0; j < 8; j++) {
            float4 v = *(float4*)&Cs[k * STR + q * 32 + 4 * j];
            s += v.x * v.x + v.y * v.y + v.z * v.z + v.w * v.w;
        }
        s += __shfl_xor_sync(~0u, s, 1);
        s += __shfl_xor_sync(~0u, s, 2);
        if (q == 0) cn2[k] = s;
    }
    __syncthreads();

    // ---- GEMM1: S^T[k][n] = C[k][d] * xn[n][d]^T ; warp w: n in [8w,8w+8) ----
    float acc[4][4];
    #pragma unroll
    for (int mt = 0; mt < 4; mt++)
        #pragma unroll
        for (int q = 0; q < 4; q++) acc[mt][q] = 0.f;

    #pragma unroll
    for (int s = 0; s < 16; s++) {
        const int col = s * 8 + c0;
        uint32_t a[4][4], bf[2];
        #pragma unroll
        for (int mt = 0; mt < 4; mt++) {
            const float* p = &Cs[(mt * 16 + r0) * STR + col];
            a[mt][0] = __float_as_uint(p[0]);
            a[mt][1] = __float_as_uint(p[8 * STR]);
            a[mt][2] = __float_as_uint(p[4]);
            a[mt][3] = __float_as_uint(p[8 * STR + 4]);
        }
        {
            const float* p = &xs[(nb + r0) * STR + col];
            bf[0] = __float_as_uint(p[0]);
            bf[1] = __float_as_uint(p[4]);
        }
        #pragma unroll
        for (int mt = 0; mt < 4; mt++) mma8(acc[mt], a[mt], bf);
    }

    // ---- softmax per n-column over k=64 (within warp) ----
    // dist = cn2[k] - 2*S (||xn||^2 shift dropped: softmax shift-invariant)
    float mx0 = -1e30f, mx1 = -1e30f;
    #pragma unroll
    for (int mt = 0; mt < 4; mt++) {
        float cA = cn2[mt * 16 + r0], cB = cn2[mt * 16 + r0 + 8];
        acc[mt][0] = cA - 2.f * acc[mt][0];
        acc[mt][1] = cA - 2.f * acc[mt][1];
        acc[mt][2] = cB - 2.f * acc[mt][2];
        acc[mt][3] = cB - 2.f * acc[mt][3];
        mx0 = fmaxf(mx0, fmaxf(acc[mt][0], acc[mt][2]));
        mx1 = fmaxf(mx1, fmaxf(acc[mt][1], acc[mt][3]));
    }
    #pragma unroll
    for (int o = 4; o <= 16; o <<= 1) {
        mx0 = fmaxf(mx0, __shfl_xor_sync(~0u, mx0, o));
        mx1 = fmaxf(mx1, __shfl_xor_sync(~0u, mx1, o));
    }
    float s0 = 0.f, s1 = 0.f;
    #pragma unroll
    for (int mt = 0; mt < 4; mt++) {
        acc[mt][0] = __expf(acc[mt][0] - mx0);
        acc[mt][1] = __expf(acc[mt][1] - mx1);
        acc[mt][2] = __expf(acc[mt][2] - mx0);
        acc[mt][3] = __expf(acc[mt][3] - mx1);
        s0 += acc[mt][0] + acc[mt][2];
        s1 += acc[mt][1] + acc[mt][3];
    }
    #pragma unroll
    for (int o = 4; o <= 16; o <<= 1) {
        s0 += __shfl_xor_sync(~0u, s0, o);
        s1 += __shfl_xor_sync(~0u, s1, o);
    }
    s0 = 1.f / s0;
    s1 = 1.f / s1;

    // assign -> At[k][n] (tf32-rounded) + row sums -> ssm
    #pragma unroll
    for (int mt = 0; mt < 4; mt++) {
        float a0 = acc[mt][0] * s0, a1 = acc[mt][1] * s1;
        float a2 = acc[mt][2] * s0, a3 = acc[mt][3] * s1;
        float rs0 = a0 + a1, rs1 = a2 + a3;
        int rr = mt * 16 + r0, cc = nb + 2 * c0;
        At[rr * STRA + cc]           = __uint_as_float(tf32r(a0));
        At[rr * STRA + cc + 1]       = __uint_as_float(tf32r(a1));
        At[(rr + 8) * STRA + cc]     = __uint_as_float(tf32r(a2));
        At[(rr + 8) * STRA + cc + 1] = __uint_as_float(tf32r(a3));
        rs0 += __shfl_xor_sync(~0u, rs0, 1);
        rs0 += __shfl_xor_sync(~0u, rs0, 2);
        rs1 += __shfl_xor_sync(~0u, rs1, 1);
        rs1 += __shfl_xor_sync(~0u, rs1, 2);
        if (c0 == 0) {
            atomicAdd(&ssm[rr], rs0);
            atomicAdd(&ssm[rr + 8], rs1);
        }
    }
    __syncthreads();

    // ---- GEMM2: P[k][d] = At[k][n] * Xn[n][d] ; warp w: d in [16w,16w+16) ----
    const int db = w * 16;
    float pc[4][2][4];
    #pragma unroll
    for (int mt = 0; mt < 4; mt++)
        #pragma unroll
        for (int nt = 0; nt < 2; nt++)
            #pragma unroll
            for (int q = 0; q < 4; q++) pc[mt][nt][q] = 0.f;

    #pragma unroll
    for (int s = 0; s < 8; s++) {
        const int col = s * 8 + c0;
        uint32_t a[4][4], bf0[2], bf1[2];
        #pragma unroll
        for (int mt = 0; mt < 4; mt++) {
            const float* p = &At[(mt * 16 + r0) * STRA + col];
            a[mt][0] = __float_as_uint(p[0]);
            a[mt][1] = __float_as_uint(p[8 * STRA]);
            a[mt][2] = __float_as_uint(p[4]);
            a[mt][3] = __float_as_uint(p[8 * STRA + 4]);
        }
        bf0[0] = __float_as_uint(xs[col * STR + db + r0]);
        bf0[1] = __float_as_uint(xs[(col + 4) * STR + db + r0]);
        bf1[0] = __float_as_uint(xs[col * STR + db + 8 + r0]);
        bf1[1] = __float_as_uint(xs[(col + 4) * STR + db + 8 + r0]);
        #pragma unroll
        for (int mt = 0; mt < 4; mt++) {
            mma8(pc[mt][0], a[mt], bf0);
            mma8(pc[mt][1], a[mt], bf1);
        }
    }

    // store per-tile partials
    float* Pb = g_Pp + (size_t)(b * TILES + tile) * KK * DD;
    #pragma unroll
    for (int mt = 0; mt < 4; mt++)
        #pragma unroll
        for (int nt = 0; nt < 2; nt++) {
            int rr = mt * 16 + r0, dd2 = db + nt * 8 + 2 * c0;
            *(float2*)&Pb[rr * DD + dd2]       = make_float2(pc[mt][nt][0], pc[mt][nt][1]);
            *(float2*)&Pb[(rr + 8) * DD + dd2] = make_float2(pc[mt][nt][2], pc[mt][nt][3]);
        }
    if (tid < 64) g_sp[(b * TILES + tile) * KK + tid] = ssm[tid];
}

// ---------------------------------------------------------------------------
// fin: grid (b=8, k=64) = 512 blocks, 128 threads = 4 warps. Warp h reduces
// tiles [8h, 8h+8) with float4 loads (high MLP); smem combine; warp 0 does
// v = P - s*c, intra-normalize, exact global scale 1/8, write out.
// ---------------------------------------------------------------------------
__global__ __launch_bounds__(128, 8)
void nv_fin(const float* __restrict__ cent, float* __restrict__ out) {
    __shared__ float4 ps[4][32];
    __shared__ float s_s;
    const int b = blockIdx.x, k = blockIdx.y;
    const int l = threadIdx.x & 31, h = threadIdx.x >> 5;

    const float4* P4 = (const float4*)g_Pp;
    float4 a = make_float4(0.f, 0.f, 0.f, 0.f);
    #pragma unroll
    for (int t = h * 8; t < h * 8 + 8; t++) {
        float4 v = P4[((size_t)(b * TILES + t) * KK + k) * 32 + l];
        a.x += v.x; a.y += v.y; a.z += v.z; a.w += v.w;
    }
    ps[h][l] = a;

    if (h == 0) {
        float sv = g_sp[(b * TILES + l) * KK + k];
        #pragma unroll
        for (int o = 16; o; o >>= 1) sv += __shfl_xor_sync(~0u, sv, o);
        if (l == 0) s_s = sv;
    }
    __syncthreads();

    if (h == 0) {
        float4 v0 = ps[0][l], v1 = ps[1][l], v2 = ps[2][l], v3 = ps[3][l];
        const float4 c = ((const float4*)cent)[k * 32 + l];
        float sk = s_s;
        float4 v = make_float4(v0.x + v1.x + v2.x + v3.x - sk * c.x,
                               v0.y + v1.y + v2.y + v3.y - sk * c.y,
                               v0.z + v1.z + v2.z + v3.z - sk * c.z,
                               v0.w + v1.w + v2.w + v3.w - sk * c.w);
        float ss = v.x * v.x + v.y * v.y + v.z * v.z + v.w * v.w;
        #pragma unroll
        for (int o = 16; o; o >>= 1) ss += __shfl_xor_sync(~0u, ss, o);
        float sc = 0.125f / fmaxf(sqrtf(ss), 1e-12f);
        v.x *= sc; v.y *= sc; v.z *= sc; v.w *= sc;
        ((float4*)out)[(size_t)b * KK * 32 + k * 32 + l] = v;
    }
}

// ---------------------------------------------------------------------------
extern "C" void kernel_launch(void* const* d_in, const int* in_sizes, int n_in,
                              void* d_out, int out_size) {
    (void)in_sizes; (void)n_in; (void)out_size;
    const float* x    = (const float*)d_in[0];
    const float* cent = (const float*)d_in[1];
    float* out        = (float*)d_out;

    cudaFuncSetAttribute(nv_main, cudaFuncAttributeMaxDynamicSharedMemorySize,
                         (int)(SMF * sizeof(float)));
    nv_main<<<dim3(TILES, BB), 256, SMF * sizeof(float)>>>(x, cent);
    nv_fin<<<dim3(BB, KK), 128>>>(cent, out);
}

// round 8
// speedup vs baseline: 1.0152x; 1.0017x over previous
#include <cuda_runtime.h>
#include <cstdint>
#include <math.h>

#define BB 8
#define NN 2048
#define DD 128
#define KK 64
#define TT 64
#define TILES 32   // NN / TT

// per-tile partials (fully rewritten every launch -> no zero kernel)
__device__ float g_Pp[BB * TILES * KK * DD];   // 8 MB (L2-resident)
__device__ float g_sp[BB * TILES * KK];
__device__ unsigned int g_arr[BB];             // arrive counters (reset in-kernel)
__device__ unsigned int g_dep[BB];             // depart counters (reset in-kernel)

#define STR  132  // smem row stride (floats) for Cs/xs
#define STRA 68   // smem row stride for At (n=64 + pad)

// smem float offsets
#define O_CN2 0
#define O_SSM 64
#define O_CS  128
#define O_AT  (O_CS + KK * STR)      // 64*132
#define O_XS  (O_AT + KK * STRA)     // 64*68
#define SMF   (O_XS + TT * STR)      // 21376 floats = 85504 B

__device__ __forceinline__ uint32_t tf32r(float f) {
    uint32_t u;
    asm("cvt.rna.tf32.f32 %0, %1;" : "=r"(u) : "f"(f));
    return u;
}
__device__ __forceinline__ void mma8(float* d, const uint32_t* a, const uint32_t* b) {
    asm volatile(
        "mma.sync.aligned.m16n8k8.row.col.f32.tf32.tf32.f32 "
        "{%0,%1,%2,%3}, {%4,%5,%6,%7}, {%8,%9}, {%0,%1,%2,%3};"
        : "+f"(d[0]), "+f"(d[1]), "+f"(d[2]), "+f"(d[3])
        : "r"(a[0]), "r"(a[1]), "r"(a[2]), "r"(a[3]), "r"(b[0]), "r"(b[1]));
}

// ---------------------------------------------------------------------------
// Single fused kernel: grid = (32 tiles, 8 batches), 256 threads, 2 CTAs/SM.
// Phase 1 (per 64-row tile): normalize, GEMM1, softmax, GEMM2 -> partials.
// Phase 2 (after per-b spin barrier): CTA (b,tile) reduces k-slice
// [2*tile, 2*tile+2) across all 32 tiles from L2, finalizes, writes out.
// ---------------------------------------------------------------------------
__global__ __launch_bounds__(256, 2)
void nv_main(const float* __restrict__ x, const float* __restrict__ cent,
             float* __restrict__ out) {
    extern __shared__ float sm[];
    float* cn2 = sm + O_CN2;
    float* ssm = sm + O_SSM;
    float* Cs  = sm + O_CS;
    float* At  = sm + O_AT;
    float* xs  = sm + O_XS;

    const int tid = threadIdx.x, w = tid >> 5, l = tid & 31;
    const int b = blockIdx.y, tile = blockIdx.x;
    const int r0 = l >> 2, c0 = l & 3;
    const int nb = w * 8;

    if (tid < 64) ssm[tid] = 0.f;

    // ---- phase A: load C (tf32-rounded); load x rows to regs, L2-normalize,
    //      single smem write. Warp w owns rows 8w..8w+8. ----
    {
        const float4* x4 = (const float4*)(x + ((size_t)b * NN + (size_t)tile * TT) * DD);
        float4 xv[8];
        #pragma unroll
        for (int i = 0; i < 8; i++) xv[i] = x4[(w * 8 + i) * 32 + l];

        const float4* c4 = (const float4*)cent;
        #pragma unroll
        for (int i = tid; i < KK * DD / 4; i += 256) {
            float4 v = c4[i];
            int k = i >> 5, d4 = (i & 31) * 4;
            float* dst = &Cs[k * STR + d4];
            dst[0] = __uint_as_float(tf32r(v.x));
            dst[1] = __uint_as_float(tf32r(v.y));
            dst[2] = __uint_as_float(tf32r(v.z));
            dst[3] = __uint_as_float(tf32r(v.w));
        }

        #pragma unroll
        for (int i = 0; i < 8; i++) {
            float4 v = xv[i];
            float ss = v.x * v.x + v.y * v.y + v.z * v.z + v.w * v.w;
            #pragma unroll
            for (int o = 16; o; o >>= 1) ss += __shfl_xor_sync(~0u, ss, o);
            float ri = 1.f / fmaxf(sqrtf(ss), 1e-12f);
            float* dst = &xs[(w * 8 + i) * STR + 4 * l];
            dst[0] = __uint_as_float(tf32r(v.x * ri));
            dst[1] = __uint_as_float(tf32r(v.y * ri));
            dst[2] = __uint_as_float(tf32r(v.z * ri));
            dst[3] = __uint_as_float(tf32r(v.w * ri));
        }
    }
    __syncthreads();

    // ---- phase B: cn2[k] = ||c_k||^2 ----
    {
        int k = tid >> 2, q = tid & 3;
        float s = 0.f;
        #pragma unroll
        for (int j = 0; j < 8; j++) {
            float4 v = *(float4*)&Cs[k * STR + q * 32 + 4 * j];
            s += v.x * v.x + v.y * v.y + v.z * v.z + v.w * v.w;
        }
        s += __shfl_xor_sync(~0u, s, 1);
        s += __shfl_xor_sync(~0u, s, 2);
        if (q == 0) cn2[k] = s;
    }
    __syncthreads();

    // ---- GEMM1: S^T[k][n] = C[k][d] * xn[n][d]^T ; warp w: n in [8w,8w+8) ----
    float acc[4][4];
    #pragma unroll
    for (int mt = 0; mt < 4; mt++)
        #pragma unroll
        for (int q = 0; q < 4; q++) acc[mt][q] = 0.f;

    #pragma unroll
    for (int s = 0; s < 16; s++) {
        const int col = s * 8 + c0;
        uint32_t a[4][4], bf[2];
        #pragma unroll
        for (int mt = 0; mt < 4; mt++) {
            const float* p = &Cs[(mt * 16 + r0) * STR + col];
            a[mt][0] = __float_as_uint(p[0]);
            a[mt][1] = __float_as_uint(p[8 * STR]);
            a[mt][2] = __float_as_uint(p[4]);
            a[mt][3] = __float_as_uint(p[8 * STR + 4]);
        }
        {
            const float* p = &xs[(nb + r0) * STR + col];
            bf[0] = __float_as_uint(p[0]);
            bf[1] = __float_as_uint(p[4]);
        }
        #pragma unroll
        for (int mt = 0; mt < 4; mt++) mma8(acc[mt], a[mt], bf);
    }

    // ---- softmax per n-column over k=64 (within warp) ----
    float mx0 = -1e30f, mx1 = -1e30f;
    #pragma unroll
    for (int mt = 0; mt < 4; mt++) {
        float cA = cn2[mt * 16 + r0], cB = cn2[mt * 16 + r0 + 8];
        acc[mt][0] = cA - 2.f * acc[mt][0];
        acc[mt][1] = cA - 2.f * acc[mt][1];
        acc[mt][2] = cB - 2.f * acc[mt][2];
        acc[mt][3] = cB - 2.f * acc[mt][3];
        mx0 = fmaxf(mx0, fmaxf(acc[mt][0], acc[mt][2]));
        mx1 = fmaxf(mx1, fmaxf(acc[mt][1], acc[mt][3]));
    }
    #pragma unroll
    for (int o = 4; o <= 16; o <<= 1) {
        mx0 = fmaxf(mx0, __shfl_xor_sync(~0u, mx0, o));
        mx1 = fmaxf(mx1, __shfl_xor_sync(~0u, mx1, o));
    }
    float s0 = 0.f, s1 = 0.f;
    #pragma unroll
    for (int mt = 0; mt < 4; mt++) {
        acc[mt][0] = __expf(acc[mt][0] - mx0);
        acc[mt][1] = __expf(acc[mt][1] - mx1);
        acc[mt][2] = __expf(acc[mt][2] - mx0);
        acc[mt][3] = __expf(acc[mt][3] - mx1);
        s0 += acc[mt][0] + acc[mt][2];
        s1 += acc[mt][1] + acc[mt][3];
    }
    #pragma unroll
    for (int o = 4; o <= 16; o <<= 1) {
        s0 += __shfl_xor_sync(~0u, s0, o);
        s1 += __shfl_xor_sync(~0u, s1, o);
    }
    s0 = 1.f / s0;
    s1 = 1.f / s1;

    // assign -> At[k][n] (tf32-rounded) + row sums -> ssm
    #pragma unroll
    for (int mt = 0; mt < 4; mt++) {
        float a0 = acc[mt][0] * s0, a1 = acc[mt][1] * s1;
        float a2 = acc[mt][2] * s0, a3 = acc[mt][3] * s1;
        float rs0 = a0 + a1, rs1 = a2 + a3;
        int rr = mt * 16 + r0, cc = nb + 2 * c0;
        At[rr * STRA + cc]           = __uint_as_float(tf32r(a0));
        At[rr * STRA + cc + 1]       = __uint_as_float(tf32r(a1));
        At[(rr + 8) * STRA + cc]     = __uint_as_float(tf32r(a2));
        At[(rr + 8) * STRA + cc + 1] = __uint_as_float(tf32r(a3));
        rs0 += __shfl_xor_sync(~0u, rs0, 1);
        rs0 += __shfl_xor_sync(~0u, rs0, 2);
        rs1 += __shfl_xor_sync(~0u, rs1, 1);
        rs1 += __shfl_xor_sync(~0u, rs1, 2);
        if (c0 == 0) {
            atomicAdd(&ssm[rr], rs0);
            atomicAdd(&ssm[rr + 8], rs1);
        }
    }
    __syncthreads();

    // ---- GEMM2: P[k][d] = At[k][n] * Xn[n][d] ; warp w: d in [16w,16w+16) ----
    const int db = w * 16;
    float pc[4][2][4];
    #pragma unroll
    for (int mt = 0; mt < 4; mt++)
        #pragma unroll
        for (int nt = 0; nt < 2; nt++)
            #pragma unroll
            for (int q = 0; q < 4; q++) pc[mt][nt][q] = 0.f;

    #pragma unroll
    for (int s = 0; s < 8; s++) {
        const int col = s * 8 + c0;
        uint32_t a[4][4], bf0[2], bf1[2];
        #pragma unroll
        for (int mt = 0; mt < 4; mt++) {
            const float* p = &At[(mt * 16 + r0) * STRA + col];
            a[mt][0] = __float_as_uint(p[0]);
            a[mt][1] = __float_as_uint(p[8 * STRA]);
            a[mt][2] = __float_as_uint(p[4]);
            a[mt][3] = __float_as_uint(p[8 * STRA + 4]);
        }
        bf0[0] = __float_as_uint(xs[col * STR + db + r0]);
        bf0[1] = __float_as_uint(xs[(col + 4) * STR + db + r0]);
        bf1[0] = __float_as_uint(xs[col * STR + db + 8 + r0]);
        bf1[1] = __float_as_uint(xs[(col + 4) * STR + db + 8 + r0]);
        #pragma unroll
        for (int mt = 0; mt < 4; mt++) {
            mma8(pc[mt][0], a[mt], bf0);
            mma8(pc[mt][1], a[mt], bf1);
        }
    }

    // store per-tile partials
    float* Pb = g_Pp + (size_t)(b * TILES + tile) * KK * DD;
    #pragma unroll
    for (int mt = 0; mt < 4; mt++)
        #pragma unroll
        for (int nt = 0; nt < 2; nt++) {
            int rr = mt * 16 + r0, dd2 = db + nt * 8 + 2 * c0;
            *(float2*)&Pb[rr * DD + dd2]       = make_float2(pc[mt][nt][0], pc[mt][nt][1]);
            *(float2*)&Pb[(rr + 8) * DD + dd2] = make_float2(pc[mt][nt][2], pc[mt][nt][3]);
        }
    if (tid < 64) g_sp[(b * TILES + tile) * KK + tid] = ssm[tid];

    // ================= cross-CTA barrier (per b) =================
    // All 256 CTAs are co-resident (296 slots), so spinning is deadlock-free.
    __threadfence();
    __syncthreads();
    if (tid == 0) {
        atomicAdd(&g_arr[b], 1u);
        volatile unsigned int* va = &g_arr[b];
        while (*va < TILES) __nanosleep(64);
        __threadfence();
        // depart + reset for next graph replay (last departer resets both)
        unsigned int my = atomicAdd(&g_dep[b], 1u);
        if (my == TILES - 1) { g_arr[b] = 0u; g_dep[b] = 0u; }
    }
    __syncthreads();

    // ================= phase 2: reduce + finalize =================
    // CTA (b,tile) owns k in {2*tile, 2*tile+1}. thread: k-half = tid>>7, d = tid&127.
    {
        const int kh = tid >> 7, d = tid & 127;
        const int k = tile * 2 + kh;

        float accr = 0.f;
        #pragma unroll
        for (int t = 0; t < TILES; t++)
            accr += __ldcg(&g_Pp[((size_t)(b * TILES + t) * KK + k) * DD + d]);

        // s[k]: warp 0 of each half loads 32 tile values and reduces
        float* s_s = sm;        // reuse smem (2 floats)
        float* ps  = sm + 4;    // 8 warp partials
        if ((tid & 127) < 32) {
            float sv = __ldcg(&g_sp[(b * TILES + l) * KK + k]);
            #pragma unroll
            for (int o = 16; o; o >>= 1) sv += __shfl_xor_sync(~0u, sv, o);
            if (l == 0) s_s[kh] = sv;
        }
        __syncthreads();

        float v = accr - s_s[kh] * cent[k * DD + d];
        float ssq = v * v;
        #pragma unroll
        for (int o = 16; o; o >>= 1) ssq += __shfl_xor_sync(~0u, ssq, o);
        if (l == 0) ps[w] = ssq;
        __syncthreads();

        float tot = ps[kh * 4 + 0] + ps[kh * 4 + 1] + ps[kh * 4 + 2] + ps[kh * 4 + 3];
        float sc = 0.125f / fmaxf(sqrtf(tot), 1e-12f);
        out[((size_t)b * KK + k) * DD + d] = v * sc;
    }
}

// ---------------------------------------------------------------------------
extern "C" void kernel_launch(void* const* d_in, const int* in_sizes, int n_in,
                              void* d_out, int out_size) {
    (void)in_sizes; (void)n_in; (void)out_size;
    const float* x    = (const float*)d_in[0];
    const float* cent = (const float*)d_in[1];
    float* out        = (float*)d_out;

    cudaFuncSetAttribute(nv_main, cudaFuncAttributeMaxDynamicSharedMemorySize,
                         (int)(SMF * sizeof(float)));
    nv_main<<<dim3(TILES, BB), 256, SMF * sizeof(float)>>>(x, cent, out);
}

// round 9
// speedup vs baseline: 1.0399x; 1.0243x over previous
#include <cuda_runtime.h>
#include <cuda_fp16.h>
#include <cstdint>
#include <math.h>

#define BB 8
#define NN 2048
#define DD 128
#define KK 64
#define TT 32
#define TILES 64   // NN / TT

// per-tile partials (fully rewritten every launch -> no zero kernel)
__device__ float g_Pp[BB * TILES * KK * DD];   // 16 MB (L2-resident)
__device__ float g_sp[BB * TILES * KK];
__device__ unsigned int g_arr[BB];
__device__ unsigned int g_dep[BB];

// half strides: Cs/xs rows = 136 halves (68 words, 68%32=4 -> bank 4g+t OK)
//               At rows    = 40 halves  (20 words, 20%32=20 -> 20g+t distinct OK)
#define STRC 136
#define STRA 40

// smem byte offsets
#define O_CS   0                       // 64*136*2 = 17408
#define O_XS   17408                   // 32*136*2 = 8704
#define O_AT   26112                   // 64*40*2  = 5120
#define O_CN2  31232                   // 64 floats
#define O_SSM  31488                   // 64 floats
#define O_RED  31744                   // 8 floats
#define SMEMB  31776

__device__ __forceinline__ void mma16(float* d, const uint32_t* a, const uint32_t* b) {
    asm volatile(
        "mma.sync.aligned.m16n8k16.row.col.f32.f16.f16.f32 "
        "{%0,%1,%2,%3}, {%4,%5,%6,%7}, {%8,%9}, {%0,%1,%2,%3};"
        : "+f"(d[0]), "+f"(d[1]), "+f"(d[2]), "+f"(d[3])
        : "r"(a[0]), "r"(a[1]), "r"(a[2]), "r"(a[3]), "r"(b[0]), "r"(b[1]));
}

// ---------------------------------------------------------------------------
// Fused kernel: grid = (64 tiles, 8 b) = 512 CTAs, 128 threads, <=4 CTAs/SM.
// Phase 1 (32-row tile): normalize -> fp16 smem, GEMM1 (m16n8k16), softmax,
// GEMM2 -> per-tile fp32 partials. Per-b spin barrier (64 arrivals).
// Phase 2: CTA (b,tile) reduces k=tile over 64 tiles, finalizes, writes out.
// ---------------------------------------------------------------------------
__global__ void __launch_bounds__(128, 4)
nv_main(const float* __restrict__ x, const float* __restrict__ cent,
        float* __restrict__ out) {
    extern __shared__ char smc[];
    half*  Cs  = (half*)(smc + O_CS);
    half*  xs  = (half*)(smc + O_XS);
    half*  At  = (half*)(smc + O_AT);
    float* cn2 = (float*)(smc + O_CN2);
    float* ssm = (float*)(smc + O_SSM);
    float* red = (float*)(smc + O_RED);

    const int tid = threadIdx.x, w = tid >> 5, l = tid & 31;
    const int g = l >> 2, t = l & 3;           // mma groupID / thread-in-group
    const int b = blockIdx.y, tile = blockIdx.x;
    const int nb = w * 8;

    if (tid < 64) ssm[tid] = 0.f;

    // ---- phase A: x rows -> regs; C -> fp16 smem; normalize x -> fp16 smem ----
    {
        const float4* x4 = (const float4*)(x + ((size_t)b * NN + (size_t)tile * TT) * DD);
        float4 xv[8];
        #pragma unroll
        for (int i = 0; i < 8; i++) xv[i] = x4[(w * 8 + i) * 32 + l];

        const float4* c4 = (const float4*)cent;
        #pragma unroll
        for (int i = tid; i < KK * DD / 4; i += 128) {
            float4 v = c4[i];
            int k = i >> 5, d4 = (i & 31) * 4;
            *(half2*)&Cs[k * STRC + d4]     = __floats2half2_rn(v.x, v.y);
            *(half2*)&Cs[k * STRC + d4 + 2] = __floats2half2_rn(v.z, v.w);
        }

        #pragma unroll
        for (int i = 0; i < 8; i++) {
            float4 v = xv[i];
            float ss = v.x * v.x + v.y * v.y + v.z * v.z + v.w * v.w;
            #pragma unroll
            for (int o = 16; o; o >>= 1) ss += __shfl_xor_sync(~0u, ss, o);
            float ri = 1.f / fmaxf(sqrtf(ss), 1e-12f);
            int r = w * 8 + i;
            *(half2*)&xs[r * STRC + 4 * l]     = __floats2half2_rn(v.x * ri, v.y * ri);
            *(half2*)&xs[r * STRC + 4 * l + 2] = __floats2half2_rn(v.z * ri, v.w * ri);
        }
    }
    __syncthreads();

    // ---- cn2[k] = ||c_k||^2 (from rounded halves, consistent with MMA) ----
    {
        int kc = tid >> 1, q = tid & 1;
        float s = 0.f;
        #pragma unroll
        for (int j = 0; j < 32; j++) {
            float2 f = __half22float2(*(const half2*)&Cs[kc * STRC + q * 64 + 2 * j]);
            s += f.x * f.x + f.y * f.y;
        }
        s += __shfl_xor_sync(~0u, s, 1);
        if (q == 0) cn2[kc] = s;
    }
    __syncthreads();

    // ---- GEMM1: S^T[k][n] = C[k][d] * xn[n][d]^T ; warp w: n in [8w,8w+8) ----
    const uint32_t* Cw = (const uint32_t*)Cs;
    const uint32_t* Xw = (const uint32_t*)xs;
    float acc[4][4];
    #pragma unroll
    for (int mt = 0; mt < 4; mt++)
        #pragma unroll
        for (int q = 0; q < 4; q++) acc[mt][q] = 0.f;

    #pragma unroll
    for (int s = 0; s < 8; s++) {
        const int cw = 8 * s + t;
        uint32_t a[4][4], bf[2];
        #pragma unroll
        for (int mt = 0; mt < 4; mt++) {
            int base = (mt * 16 + g) * 68 + cw;
            a[mt][0] = Cw[base];
            a[mt][1] = Cw[base + 8 * 68];
            a[mt][2] = Cw[base + 4];
            a[mt][3] = Cw[base + 8 * 68 + 4];
        }
        int bb2 = (nb + g) * 68 + cw;
        bf[0] = Xw[bb2];
        bf[1] = Xw[bb2 + 4];
        #pragma unroll
        for (int mt = 0; mt < 4; mt++) mma16(acc[mt], a[mt], bf);
    }

    // ---- softmax per n-column over k=64 (warp-local) ----
    // dist = cn2[k] - 2*S (||xn||^2 shift dropped: softmax shift-invariant)
    float mx0 = -1e30f, mx1 = -1e30f;
    #pragma unroll
    for (int mt = 0; mt < 4; mt++) {
        float cA = cn2[mt * 16 + g], cB = cn2[mt * 16 + g + 8];
        acc[mt][0] = cA - 2.f * acc[mt][0];
        acc[mt][1] = cA - 2.f * acc[mt][1];
        acc[mt][2] = cB - 2.f * acc[mt][2];
        acc[mt][3] = cB - 2.f * acc[mt][3];
        mx0 = fmaxf(mx0, fmaxf(acc[mt][0], acc[mt][2]));
        mx1 = fmaxf(mx1, fmaxf(acc[mt][1], acc[mt][3]));
    }
    #pragma unroll
    for (int o = 4; o <= 16; o <<= 1) {
        mx0 = fmaxf(mx0, __shfl_xor_sync(~0u, mx0, o));
        mx1 = fmaxf(mx1, __shfl_xor_sync(~0u, mx1, o));
    }
    float s0 = 0.f, s1 = 0.f;
    #pragma unroll
    for (int mt = 0; mt < 4; mt++) {
        acc[mt][0] = __expf(acc[mt][0] - mx0);
        acc[mt][1] = __expf(acc[mt][1] - mx1);
        acc[mt][2] = __expf(acc[mt][2] - mx0);
        acc[mt][3] = __expf(acc[mt][3] - mx1);
        s0 += acc[mt][0] + acc[mt][2];
        s1 += acc[mt][1] + acc[mt][3];
    }
    #pragma unroll
    for (int o = 4; o <= 16; o <<= 1) {
        s0 += __shfl_xor_sync(~0u, s0, o);
        s1 += __shfl_xor_sync(~0u, s1, o);
    }
    s0 = 1.f / s0;
    s1 = 1.f / s1;

    // assign -> At[k][n] (fp16) + row sums -> ssm
    #pragma unroll
    for (int mt = 0; mt < 4; mt++) {
        float a0 = acc[mt][0] * s0, a1 = acc[mt][1] * s1;
        float a2 = acc[mt][2] * s0, a3 = acc[mt][3] * s1;
        float rs0 = a0 + a1, rs1 = a2 + a3;
        int rr = mt * 16 + g;
        *(half2*)&At[rr * STRA + nb + 2 * t]       = __floats2half2_rn(a0, a1);
        *(half2*)&At[(rr + 8) * STRA + nb + 2 * t] = __floats2half2_rn(a2, a3);
        rs0 += __shfl_xor_sync(~0u, rs0, 1);
        rs0 += __shfl_xor_sync(~0u, rs0, 2);
        rs1 += __shfl_xor_sync(~0u, rs1, 1);
        rs1 += __shfl_xor_sync(~0u, rs1, 2);
        if (t == 0) {
            atomicAdd(&ssm[rr], rs0);
            atomicAdd(&ssm[rr + 8], rs1);
        }
    }
    __syncthreads();

    // ---- GEMM2: P[k][d] = At[k][n] * Xn[n][d] ; warp w: d in [32w,32w+32) ----
    const uint32_t* Aw = (const uint32_t*)At;
    const unsigned short* Xu = (const unsigned short*)xs;
    const int db = 32 * w;
    float pc[4][4][4];
    #pragma unroll
    for (int mt = 0; mt < 4; mt++)
        #pragma unroll
        for (int nt = 0; nt < 4; nt++)
            #pragma unroll
            for (int q = 0; q < 4; q++) pc[mt][nt][q] = 0.f;

    #pragma unroll
    for (int s = 0; s < 2; s++) {
        uint32_t a[4][4];
        #pragma unroll
        for (int mt = 0; mt < 4; mt++) {
            int base = (mt * 16 + g) * 20 + 8 * s + t;
            a[mt][0] = Aw[base];
            a[mt][1] = Aw[base + 160];
            a[mt][2] = Aw[base + 4];
            a[mt][3] = Aw[base + 164];
        }
        #pragma unroll
        for (int nt = 0; nt < 4; nt++) {
            int dcol = db + 8 * nt + g;
            int rh = (16 * s + 2 * t) * STRC + dcol;
            uint32_t lo0 = Xu[rh],            hi0 = Xu[rh + STRC];
            uint32_t lo1 = Xu[rh + 8 * STRC], hi1 = Xu[rh + 9 * STRC];
            uint32_t bfr[2] = { lo0 | (hi0 << 16), lo1 | (hi1 << 16) };
            #pragma unroll
            for (int mt = 0; mt < 4; mt++) mma16(pc[mt][nt], a[mt], bfr);
        }
    }

    // store per-tile partials
    float* Pb = g_Pp + (size_t)(b * TILES + tile) * KK * DD;
    #pragma unroll
    for (int mt = 0; mt < 4; mt++)
        #pragma unroll
        for (int nt = 0; nt < 4; nt++) {
            int rr = mt * 16 + g, dd2 = db + 8 * nt + 2 * t;
            *(float2*)&Pb[rr * DD + dd2]       = make_float2(pc[mt][nt][0], pc[mt][nt][1]);
            *(float2*)&Pb[(rr + 8) * DD + dd2] = make_float2(pc[mt][nt][2], pc[mt][nt][3]);
        }
    if (tid < 64) g_sp[(b * TILES + tile) * KK + tid] = ssm[tid];

    // ================= cross-CTA barrier (per b, 64 arrivals) =================
    __threadfence();
    __syncthreads();
    if (tid == 0) {
        atomicAdd(&g_arr[b], 1u);
        volatile unsigned int* va = &g_arr[b];
        while (*va < TILES) __nanosleep(64);
        __threadfence();
        unsigned int my = atomicAdd(&g_dep[b], 1u);
        if (my == TILES - 1) { g_arr[b] = 0u; g_dep[b] = 0u; }
    }
    __syncthreads();

    // ================= phase 2: CTA (b,tile) finalizes k = tile =================
    {
        const int k = tile, d = tid;   // 128 threads = 128 d-elements
        float a0 = 0.f, a1 = 0.f, a2 = 0.f, a3 = 0.f;
        #pragma unroll
        for (int tt = 0; tt < TILES; tt += 4) {
            a0 += __ldcg(&g_Pp[((size_t)(b * TILES + tt + 0) * KK + k) * DD + d]);
            a1 += __ldcg(&g_Pp[((size_t)(b * TILES + tt + 1) * KK + k) * DD + d]);
            a2 += __ldcg(&g_Pp[((size_t)(b * TILES + tt + 2) * KK + k) * DD + d]);
            a3 += __ldcg(&g_Pp[((size_t)(b * TILES + tt + 3) * KK + k) * DD + d]);
        }
        float accr = (a0 + a1) + (a2 + a3);

        float sv = 0.f;
        if (tid < 64) sv = __ldcg(&g_sp[(b * TILES + tid) * KK + k]);
        #pragma unroll
        for (int o = 16; o; o >>= 1) sv += __shfl_xor_sync(~0u, sv, o);
        if (l == 0 && w < 2) red[w] = sv;
        __syncthreads();
        float sk = red[0] + red[1];

        float v = accr - sk * cent[k * DD + d];
        float ssq = v * v;
        #pragma unroll
        for (int o = 16; o; o >>= 1) ssq += __shfl_xor_sync(~0u, ssq, o);
        if (l == 0) red[4 + w] = ssq;
        __syncthreads();
        float tot = (red[4] + red[5]) + (red[6] + red[7]);
        float sc = 0.125f / fmaxf(sqrtf(tot), 1e-12f);   // exact global norm = 8
        out[((size_t)b * KK + k) * DD + d] = v * sc;
    }
}

// ---------------------------------------------------------------------------
extern "C" void kernel_launch(void* const* d_in, const int* in_sizes, int n_in,
                              void* d_out, int out_size) {
    (void)in_sizes; (void)n_in; (void)out_size;
    const float* x    = (const float*)d_in[0];
    const float* cent = (const float*)d_in[1];
    float* out        = (float*)d_out;

    cudaFuncSetAttribute(nv_main, cudaFuncAttributeMaxDynamicSharedMemorySize, SMEMB);
    nv_main<<<dim3(TILES, BB), 128, SMEMB>>>(x, cent, out);
}

// round 10
// speedup vs baseline: 1.1385x; 1.0949x over previous
#include <cuda_runtime.h>
#include <cuda_fp16.h>
#include <cstdint>
#include <math.h>

#define BB 8
#define NN 2048
#define DD 128
#define KK 64
#define TT 32
#define TILES 64   // NN / TT

// per-tile partials (fully rewritten every launch -> no zero kernel)
__device__ float g_Pp[BB * TILES * KK * DD];   // 16 MB (L2-resident)
__device__ float g_sp[BB * TILES * KK];
__device__ unsigned int g_arr[BB];
__device__ unsigned int g_dep[BB];

// half strides: Cs/xs rows = 136 halves; At rows = 40 halves
#define STRC 136
#define STRA 40

// smem byte offsets
#define O_CS   0                       // 64*136*2 = 17408
#define O_XS   17408                   // 32*136*2 = 8704
#define O_AT   26112                   // 64*40*2  = 5120
#define O_CN2  31232                   // 64 floats
#define O_SSM  31488                   // 64 floats
#define O_RED  31744                   // 8 floats
#define SMEMB  31776

// ---- FFMA-only transcendentals (MUFU pipe is 0.5 op/cyc/SM on B300 - avoid it) ----
__device__ __forceinline__ float fexp(float x) {      // e^x, |x| modest
    float y = x * 1.4426950408889634f;
    y = fmaxf(y, -125.f);
    float t = y + 12582912.f;                          // round-to-nearest int
    int j = __float_as_int(t) << 23;                   // n * 2^23 (mod 512)
    float f = y - (t - 12582912.f);                    // frac in [-0.5, 0.5]
    float p = 1.3333558e-3f;
    p = fmaf(p, f, 9.6181291e-3f);
    p = fmaf(p, f, 5.5504109e-2f);
    p = fmaf(p, f, 2.4022648e-1f);
    p = fmaf(p, f, 6.9314718e-1f);
    p = fmaf(p, f, 1.0f);
    return __int_as_float(__float_as_int(p) + j);
}
__device__ __forceinline__ float frsqrt(float s) {    // 1/sqrt(s), s > 0
    float h = __int_as_float(0x5f375a86 - (__float_as_int(s) >> 1));
    h = h * fmaf(-0.5f * s, h * h, 1.5f);
    h = h * fmaf(-0.5f * s, h * h, 1.5f);
    return h;
}
__device__ __forceinline__ float frcp(float s) {      // 1/s, s > 0
    float r = __int_as_float(0x7ef311c3 - __float_as_int(s));
    r = r * fmaf(-s, r, 2.0f);
    r = r * fmaf(-s, r, 2.0f);
    return r;
}

__device__ __forceinline__ void mma16(float* d, const uint32_t* a, const uint32_t* b) {
    asm volatile(
        "mma.sync.aligned.m16n8k16.row.col.f32.f16.f16.f32 "
        "{%0,%1,%2,%3}, {%4,%5,%6,%7}, {%8,%9}, {%0,%1,%2,%3};"
        : "+f"(d[0]), "+f"(d[1]), "+f"(d[2]), "+f"(d[3])
        : "r"(a[0]), "r"(a[1]), "r"(a[2]), "r"(a[3]), "r"(b[0]), "r"(b[1]));
}

// ---------------------------------------------------------------------------
// Fused kernel: grid = (64 tiles, 8 b) = 512 CTAs, 128 threads, <=4 CTAs/SM.
// Phase 1 (32-row tile): normalize -> fp16 smem, GEMM1 (m16n8k16), softmax,
// GEMM2 -> per-tile fp32 partials. Per-b spin barrier (64 arrivals).
// Phase 2: CTA (b,tile) reduces k=tile over 64 tiles, finalizes, writes out.
// ---------------------------------------------------------------------------
__global__ void __launch_bounds__(128, 4)
nv_main(const float* __restrict__ x, const float* __restrict__ cent,
        float* __restrict__ out) {
    extern __shared__ char smc[];
    half*  Cs  = (half*)(smc + O_CS);
    half*  xs  = (half*)(smc + O_XS);
    half*  At  = (half*)(smc + O_AT);
    float* cn2 = (float*)(smc + O_CN2);
    float* ssm = (float*)(smc + O_SSM);
    float* red = (float*)(smc + O_RED);

    const int tid = threadIdx.x, w = tid >> 5, l = tid & 31;
    const int g = l >> 2, t = l & 3;           // mma groupID / thread-in-group
    const int b = blockIdx.y, tile = blockIdx.x;
    const int nb = w * 8;

    if (tid < 64) ssm[tid] = 0.f;

    // ---- phase A: x rows -> regs; C -> fp16 smem; normalize x -> fp16 smem ----
    {
        const float4* x4 = (const float4*)(x + ((size_t)b * NN + (size_t)tile * TT) * DD);
        float4 xv[8];
        #pragma unroll
        for (int i = 0; i < 8; i++) xv[i] = x4[(w * 8 + i) * 32 + l];

        const float4* c4 = (const float4*)cent;
        #pragma unroll
        for (int i = tid; i < KK * DD / 4; i += 128) {
            float4 v = c4[i];
            int k = i >> 5, d4 = (i & 31) * 4;
            *(half2*)&Cs[k * STRC + d4]     = __floats2half2_rn(v.x, v.y);
            *(half2*)&Cs[k * STRC + d4 + 2] = __floats2half2_rn(v.z, v.w);
        }

        #pragma unroll
        for (int i = 0; i < 8; i++) {
            float4 v = xv[i];
            float ss = v.x * v.x + v.y * v.y + v.z * v.z + v.w * v.w;
            #pragma unroll
            for (int o = 16; o; o >>= 1) ss += __shfl_xor_sync(~0u, ss, o);
            float ri = frsqrt(fmaxf(ss, 1e-24f));
            int r = w * 8 + i;
            *(half2*)&xs[r * STRC + 4 * l]     = __floats2half2_rn(v.x * ri, v.y * ri);
            *(half2*)&xs[r * STRC + 4 * l + 2] = __floats2half2_rn(v.z * ri, v.w * ri);
        }
    }
    __syncthreads();

    // ---- cn2[k] = ||c_k||^2 (from rounded halves, consistent with MMA) ----
    {
        int kc = tid >> 1, q = tid & 1;
        float s = 0.f;
        #pragma unroll
        for (int j = 0; j < 32; j++) {
            float2 f = __half22float2(*(const half2*)&Cs[kc * STRC + q * 64 + 2 * j]);
            s += f.x * f.x + f.y * f.y;
        }
        s += __shfl_xor_sync(~0u, s, 1);
        if (q == 0) cn2[kc] = s;
    }
    __syncthreads();

    // ---- GEMM1: S^T[k][n] = C[k][d] * xn[n][d]^T ; warp w: n in [8w,8w+8) ----
    const uint32_t* Cw = (const uint32_t*)Cs;
    const uint32_t* Xw = (const uint32_t*)xs;
    float acc[4][4];
    #pragma unroll
    for (int mt = 0; mt < 4; mt++)
        #pragma unroll
        for (int q = 0; q < 4; q++) acc[mt][q] = 0.f;

    #pragma unroll
    for (int s = 0; s < 8; s++) {
        const int cw = 8 * s + t;
        uint32_t a[4][4], bf[2];
        #pragma unroll
        for (int mt = 0; mt < 4; mt++) {
            int base = (mt * 16 + g) * 68 + cw;
            a[mt][0] = Cw[base];
            a[mt][1] = Cw[base + 8 * 68];
            a[mt][2] = Cw[base + 4];
            a[mt][3] = Cw[base + 8 * 68 + 4];
        }
        int bb2 = (nb + g) * 68 + cw;
        bf[0] = Xw[bb2];
        bf[1] = Xw[bb2 + 4];
        #pragma unroll
        for (int mt = 0; mt < 4; mt++) mma16(acc[mt], a[mt], bf);
    }

    // ---- softmax per n-column over k=64 (warp-local) ----
    // dist = cn2[k] - 2*S (||xn||^2 shift dropped: softmax shift-invariant)
    float mx0 = -1e30f, mx1 = -1e30f;
    #pragma unroll
    for (int mt = 0; mt < 4; mt++) {
        float cA = cn2[mt * 16 + g], cB = cn2[mt * 16 + g + 8];
        acc[mt][0] = cA - 2.f * acc[mt][0];
        acc[mt][1] = cA - 2.f * acc[mt][1];
        acc[mt][2] = cB - 2.f * acc[mt][2];
        acc[mt][3] = cB - 2.f * acc[mt][3];
        mx0 = fmaxf(mx0, fmaxf(acc[mt][0], acc[mt][2]));
        mx1 = fmaxf(mx1, fmaxf(acc[mt][1], acc[mt][3]));
    }
    #pragma unroll
    for (int o = 4; o <= 16; o <<= 1) {
        mx0 = fmaxf(mx0, __shfl_xor_sync(~0u, mx0, o));
        mx1 = fmaxf(mx1, __shfl_xor_sync(~0u, mx1, o));
    }
    float s0 = 0.f, s1 = 0.f;
    #pragma unroll
    for (int mt = 0; mt < 4; mt++) {
        acc[mt][0] = fexp(acc[mt][0] - mx0);
        acc[mt][1] = fexp(acc[mt][1] - mx1);
        acc[mt][2] = fexp(acc[mt][2] - mx0);
        acc[mt][3] = fexp(acc[mt][3] - mx1);
        s0 += acc[mt][0] + acc[mt][2];
        s1 += acc[mt][1] + acc[mt][3];
    }
    #pragma unroll
    for (int o = 4; o <= 16; o <<= 1) {
        s0 += __shfl_xor_sync(~0u, s0, o);
        s1 += __shfl_xor_sync(~0u, s1, o);
    }
    s0 = frcp(s0);
    s1 = frcp(s1);

    // assign -> At[k][n] (fp16) + row sums -> ssm
    #pragma unroll
    for (int mt = 0; mt < 4; mt++) {
        float a0 = acc[mt][0] * s0, a1 = acc[mt][1] * s1;
        float a2 = acc[mt][2] * s0, a3 = acc[mt][3] * s1;
        float rs0 = a0 + a1, rs1 = a2 + a3;
        int rr = mt * 16 + g;
        *(half2*)&At[rr * STRA + nb + 2 * t]       = __floats2half2_rn(a0, a1);
        *(half2*)&At[(rr + 8) * STRA + nb + 2 * t] = __floats2half2_rn(a2, a3);
        rs0 += __shfl_xor_sync(~0u, rs0, 1);
        rs0 += __shfl_xor_sync(~0u, rs0, 2);
        rs1 += __shfl_xor_sync(~0u, rs1, 1);
        rs1 += __shfl_xor_sync(~0u, rs1, 2);
        if (t == 0) {
            atomicAdd(&ssm[rr], rs0);
            atomicAdd(&ssm[rr + 8], rs1);
        }
    }
    __syncthreads();

    // ---- GEMM2: P[k][d] = At[k][n] * Xn[n][d] ; warp w: d in [32w,32w+32) ----
    const uint32_t* Aw = (const uint32_t*)At;
    const unsigned short* Xu = (const unsigned short*)xs;
    const int db = 32 * w;
    float pc[4][4][4];
    #pragma unroll
    for (int mt = 0; mt < 4; mt++)
        #pragma unroll
        for (int nt = 0; nt < 4; nt++)
            #pragma unroll
            for (int q = 0; q < 4; q++) pc[mt][nt][q] = 0.f;

    #pragma unroll
    for (int s = 0; s < 2; s++) {
        uint32_t a[4][4];
        #pragma unroll
        for (int mt = 0; mt < 4; mt++) {
            int base = (mt * 16 + g) * 20 + 8 * s + t;
            a[mt][0] = Aw[base];
            a[mt][1] = Aw[base + 160];
            a[mt][2] = Aw[base + 4];
            a[mt][3] = Aw[base + 164];
        }
        #pragma unroll
        for (int nt = 0; nt < 4; nt++) {
            int dcol = db + 8 * nt + g;
            int rh = (16 * s + 2 * t) * STRC + dcol;
            uint32_t lo0 = Xu[rh],            hi0 = Xu[rh + STRC];
            uint32_t lo1 = Xu[rh + 8 * STRC], hi1 = Xu[rh + 9 * STRC];
            uint32_t bfr[2] = { lo0 | (hi0 << 16), lo1 | (hi1 << 16) };
            #pragma unroll
            for (int mt = 0; mt < 4; mt++) mma16(pc[mt][nt], a[mt], bfr);
        }
    }

    // store per-tile partials
    float* Pb = g_Pp + (size_t)(b * TILES + tile) * KK * DD;
    #pragma unroll
    for (int mt = 0; mt < 4; mt++)
        #pragma unroll
        for (int nt = 0; nt < 4; nt++) {
            int rr = mt * 16 + g, dd2 = db + 8 * nt + 2 * t;
            *(float2*)&Pb[rr * DD + dd2]       = make_float2(pc[mt][nt][0], pc[mt][nt][1]);
            *(float2*)&Pb[(rr + 8) * DD + dd2] = make_float2(pc[mt][nt][2], pc[mt][nt][3]);
        }
    if (tid < 64) g_sp[(b * TILES + tile) * KK + tid] = ssm[tid];

    // ================= cross-CTA barrier (per b, 64 arrivals) =================
    __threadfence();
    __syncthreads();
    if (tid == 0) {
        atomicAdd(&g_arr[b], 1u);
        volatile unsigned int* va = &g_arr[b];
        while (*va < TILES) __nanosleep(64);
        __threadfence();
        unsigned int my = atomicAdd(&g_dep[b], 1u);
        if (my == TILES - 1) { g_arr[b] = 0u; g_dep[b] = 0u; }
    }
    __syncthreads();

    // ================= phase 2: CTA (b,tile) finalizes k = tile =================
    {
        const int k = tile, d = tid;   // 128 threads = 128 d-elements
        float a0 = 0.f, a1 = 0.f, a2 = 0.f, a3 = 0.f;
        #pragma unroll
        for (int tt = 0; tt < TILES; tt += 4) {
            a0 += __ldcg(&g_Pp[((size_t)(b * TILES + tt + 0) * KK + k) * DD + d]);
            a1 += __ldcg(&g_Pp[((size_t)(b * TILES + tt + 1) * KK + k) * DD + d]);
            a2 += __ldcg(&g_Pp[((size_t)(b * TILES + tt + 2) * KK + k) * DD + d]);
            a3 += __ldcg(&g_Pp[((size_t)(b * TILES + tt + 3) * KK + k) * DD + d]);
        }
        float accr = (a0 + a1) + (a2 + a3);

        float sv = 0.f;
        if (tid < 64) sv = __ldcg(&g_sp[(b * TILES + tid) * KK + k]);
        #pragma unroll
        for (int o = 16; o; o >>= 1) sv += __shfl_xor_sync(~0u, sv, o);
        if (l == 0 && w < 2) red[w] = sv;
        __syncthreads();
        float sk = red[0] + red[1];

        float v = accr - sk * cent[k * DD + d];
        float ssq = v * v;
        #pragma unroll
        for (int o = 16; o; o >>= 1) ssq += __shfl_xor_sync(~0u, ssq, o);
        if (l == 0) red[4 + w] = ssq;
        __syncthreads();
        float tot = (red[4] + red[5]) + (red[6] + red[7]);
        float sc = 0.125f * frsqrt(fmaxf(tot, 1e-24f));   // exact global norm = 8
        out[((size_t)b * KK + k) * DD + d] = v * sc;
    }
}

// ---------------------------------------------------------------------------
extern "C" void kernel_launch(void* const* d_in, const int* in_sizes, int n_in,
                              void* d_out, int out_size) {
    (void)in_sizes; (void)n_in; (void)out_size;
    const float* x    = (const float*)d_in[0];
    const float* cent = (const float*)d_in[1];
    float* out        = (float*)d_out;

    cudaFuncSetAttribute(nv_main, cudaFuncAttributeMaxDynamicSharedMemorySize, SMEMB);
    nv_main<<<dim3(TILES, BB), 128, SMEMB>>>(x, cent, out);
}